// round 2
// baseline (speedup 1.0000x reference)
#include <cuda_runtime.h>
#include <cstdint>

#define NCL 10
#define KCL 8
#define MID 512
#define OUT_N 5994
#define BATCH 32
#define WW 500
#define KTOT 3584
#define NPAD 576
#define MROWS 16000

// ---------------- scratch (__device__ globals; no allocations) ----------------
__device__ float g_Wt[KTOT * NPAD];            // 8.3 MB  pre-rounded tf32 weights, k-major
__device__ float g_feat[MROWS * MID];          // 32.8 MB relu(conv) output
__device__ float g_score[MROWS * NCL];         // 0.64 MB cc scores
__device__ float g_aggP[BATCH * 5 * NCL * MID];// partial aggregations (5 w-chunks)
__device__ float g_saP[BATCH * 5 * NCL];
__device__ float g_emb0[BATCH * KCL * MID];
__device__ float g_h[BATCH * MID];

__device__ __forceinline__ uint32_t f2tf32(float x) {
    uint32_t r;
    asm("cvt.rna.tf32.f32 %0, %1;" : "=r"(r) : "f"(x));
    return r;
}
__device__ __forceinline__ uint32_t smem_u32(const void* p) {
    return (uint32_t)__cvta_generic_to_shared(p);
}
__device__ __forceinline__ void cp16(uint32_t dst, const void* src, int srcsize) {
    asm volatile("cp.async.cg.shared.global [%0], [%1], 16, %2;"
                 :: "r"(dst), "l"(src), "r"(srcsize));
}

// ---------------- kernel 0: transpose + tf32-round weights ----------------
__global__ void __launch_bounds__(256) prep_weights(const float* __restrict__ conv_w,
                                                    const float* __restrict__ cc_w) {
    int idx = blockIdx.x * 256 + threadIdx.x;        // idx = k*NPAD + n
    if (idx >= KTOT * NPAD) return;
    int k = idx / NPAD;
    int n = idx - k * NPAD;
    float v = 0.0f;
    if (n < MID)            v = conv_w[n * KTOT + k];
    else if (n < MID + NCL) v = cc_w[(n - MID) * KTOT + k];
    g_Wt[idx] = __uint_as_float(f2tf32(v));
}

// ---------------- kernel 1: main GEMM (conv + cc fused), TF32 mma.sync ----------------
#define BM 128
#define BN 64
#define BK 16
#define NSTAGE 3
#define ASTR 136   // BM+8 : stride ≡ 8 (mod 32) -> conflict-free frag loads
#define BSTR 72    // BN+8
#define NSTEPS (KTOT / BK)   // 224

__global__ void __launch_bounds__(256) conv_gemm(const float* __restrict__ feats,
                                                 const float* __restrict__ conv_b,
                                                 const float* __restrict__ cc_b) {
    __shared__ __align__(16) float As[NSTAGE][BK][ASTR];
    __shared__ __align__(16) float Bs[NSTAGE][BK][BSTR];

    const int tid = threadIdx.x;
    const int b  = blockIdx.z;
    const int w0 = blockIdx.y * BM;
    const int n0 = blockIdx.x * BN;

    const float* Abase = feats + b * 1792000 + w0;   // b * 512*7*500

    // A loader: 2 passes of (8 k-rows x 32 float4)
    const int a_row  = tid >> 5;       // 0..7
    const int a_col4 = tid & 31;
    const int wlocal = a_col4 * 4;
    const int a_sz   = (w0 + wlocal + 3 < WW) ? 16 : 0;
    // B loader: 16 k-rows x 16 float4, one per thread
    const int b_row  = tid >> 4;
    const int b_col4 = tid & 15;

    auto load_stage = [&](int s, int step) {
        int k0 = step * BK;
#pragma unroll
        for (int p = 0; p < 2; p++) {
            int row = a_row + p * 8;
            int k = k0 + row;
            int c = k / 7;
            int h = k - c * 7;
            const float* src = a_sz ? (Abase + c * 3500 + h * 500 + wlocal) : Abase;
            cp16(smem_u32(&As[s][row][wlocal]), src, a_sz);
        }
        const float* bsrc = &g_Wt[(k0 + b_row) * NPAD + n0 + b_col4 * 4];
        cp16(smem_u32(&Bs[s][b_row][b_col4 * 4]), bsrc, 16);
        asm volatile("cp.async.commit_group;");
    };

    const int lane = tid & 31, warp = tid >> 5;
    const int g = lane >> 2, t = lane & 3;
    const int wm = (warp >> 1) * 32;   // 4 warps along M
    const int wn = (warp & 1) * 32;    // 2 warps along N

    float acc[2][4][4];
#pragma unroll
    for (int mi = 0; mi < 2; mi++)
#pragma unroll
        for (int ni = 0; ni < 4; ni++)
#pragma unroll
            for (int r = 0; r < 4; r++) acc[mi][ni][r] = 0.0f;

    load_stage(0, 0);
    load_stage(1, 1);

    for (int s = 0; s < NSTEPS; s++) {
        if (s < NSTEPS - 1) { asm volatile("cp.async.wait_group 1;"); }
        else                { asm volatile("cp.async.wait_group 0;"); }
        __syncthreads();
        const int sb = s % NSTAGE;
#pragma unroll
        for (int kk = 0; kk < BK; kk += 8) {
            uint32_t af[2][4], bf[4][2];
#pragma unroll
            for (int mi = 0; mi < 2; mi++) {
                af[mi][0] = f2tf32(As[sb][kk + t    ][wm + mi * 16 + g    ]);
                af[mi][1] = f2tf32(As[sb][kk + t    ][wm + mi * 16 + g + 8]);
                af[mi][2] = f2tf32(As[sb][kk + t + 4][wm + mi * 16 + g    ]);
                af[mi][3] = f2tf32(As[sb][kk + t + 4][wm + mi * 16 + g + 8]);
            }
#pragma unroll
            for (int ni = 0; ni < 4; ni++) {
                bf[ni][0] = __float_as_uint(Bs[sb][kk + t    ][wn + ni * 8 + g]);
                bf[ni][1] = __float_as_uint(Bs[sb][kk + t + 4][wn + ni * 8 + g]);
            }
#pragma unroll
            for (int mi = 0; mi < 2; mi++)
#pragma unroll
                for (int ni = 0; ni < 4; ni++) {
                    asm volatile(
                        "mma.sync.aligned.m16n8k8.row.col.f32.tf32.tf32.f32 "
                        "{%0,%1,%2,%3}, {%4,%5,%6,%7}, {%8,%9}, {%0,%1,%2,%3};"
                        : "+f"(acc[mi][ni][0]), "+f"(acc[mi][ni][1]),
                          "+f"(acc[mi][ni][2]), "+f"(acc[mi][ni][3])
                        : "r"(af[mi][0]), "r"(af[mi][1]), "r"(af[mi][2]), "r"(af[mi][3]),
                          "r"(bf[ni][0]), "r"(bf[ni][1]));
                }
        }
        if (s + 2 < NSTEPS) load_stage((s + 2) % NSTAGE, s + 2);
    }

    // epilogue: bias + relu -> g_feat, bias -> g_score
#pragma unroll
    for (int mi = 0; mi < 2; mi++) {
        int m0 = wm + mi * 16 + g;
#pragma unroll
        for (int ni = 0; ni < 4; ni++) {
            int n = n0 + wn + ni * 8 + 2 * t;
#pragma unroll
            for (int r = 0; r < 4; r++) {
                int mm = m0 + ((r >= 2) ? 8 : 0);
                int nn = n + (r & 1);
                int wg = w0 + mm;
                if (wg < WW) {
                    float v = acc[mi][ni][r];
                    if (nn < MID) {
                        v += conv_b[nn];
                        g_feat[(b * WW + wg) * MID + nn] = fmaxf(v, 0.0f);
                    } else if (nn < MID + NCL) {
                        v += cc_b[nn - MID];
                        g_score[(b * WW + wg) * NCL + (nn - MID)] = v;
                    }
                }
            }
        }
    }
}

// ---------------- kernel 2: softmax + weighted aggregation (partial over w-chunks) ----------------
__global__ void __launch_bounds__(512) agg_kernel() {
    __shared__ float p_s[100][NCL];
    const int b = blockIdx.x, chunk = blockIdx.y;
    const int w_base = chunk * 100;
    const int tid = threadIdx.x;

    if (tid < 100) {
        const float* sc = &g_score[(b * WW + w_base + tid) * NCL];
        float v[NCL];
        float mx = -1e30f;
#pragma unroll
        for (int k = 0; k < NCL; k++) { v[k] = sc[k]; mx = fmaxf(mx, v[k]); }
        float s = 0.0f;
#pragma unroll
        for (int k = 0; k < NCL; k++) { v[k] = __expf(v[k] - mx); s += v[k]; }
        float inv = 1.0f / s;
#pragma unroll
        for (int k = 0; k < NCL; k++) p_s[tid][k] = v[k] * inv;
    }
    __syncthreads();

    if (tid < NCL) {
        float ss = 0.0f;
        for (int w = 0; w < 100; w++) ss += p_s[w][tid];
        g_saP[(b * 5 + chunk) * NCL + tid] = ss;
    }

    const int c = tid;   // 512 threads = MID channels
    float acc[NCL];
#pragma unroll
    for (int k = 0; k < NCL; k++) acc[k] = 0.0f;
    for (int w = 0; w < 100; w++) {
        float f = g_feat[(b * WW + w_base + w) * MID + c];
#pragma unroll
        for (int k = 0; k < NCL; k++) acc[k] += p_s[w][k] * f;
    }
#pragma unroll
    for (int k = 0; k < NCL; k++)
        g_aggP[((b * 5 + chunk) * NCL + k) * MID + c] = acc[k];
}

// ---------------- kernel 3: residual + L2 normalize -> emb0 ----------------
__global__ void __launch_bounds__(512) cluster_kernel(const float* __restrict__ centroids) {
    const int b = blockIdx.x, k = blockIdx.y;   // k < 8
    const int c = threadIdx.x;
    float a = 0.0f;
#pragma unroll
    for (int ch = 0; ch < 5; ch++) a += g_aggP[((b * 5 + ch) * NCL + k) * MID + c];

    __shared__ float s_sa;
    __shared__ float s_red[16];
    if (c == 0) {
        float s = 0.0f;
#pragma unroll
        for (int ch = 0; ch < 5; ch++) s += g_saP[(b * 5 + ch) * NCL + k];
        s_sa = s;
    }
    __syncthreads();

    float r = a - s_sa * centroids[k * MID + c];
    float x = r * r;
#pragma unroll
    for (int off = 16; off > 0; off >>= 1) x += __shfl_xor_sync(0xffffffffu, x, off);
    int lane = c & 31, wid = c >> 5;
    if (lane == 0) s_red[wid] = x;
    __syncthreads();
    if (wid == 0) {
        float y = (lane < 16) ? s_red[lane] : 0.0f;
#pragma unroll
        for (int off = 8; off > 0; off >>= 1) y += __shfl_xor_sync(0xffffffffu, y, off);
        if (lane == 0) s_red[0] = y;
    }
    __syncthreads();
    float inv = 1.0f / fmaxf(sqrtf(s_red[0]), 1e-12f);
    g_emb0[b * (KCL * MID) + k * MID + c] = r * inv;
}

// ---------------- kernel 4: h = emb0 @ fc_w + fc_b ----------------
__global__ void __launch_bounds__(512) fc_kernel(const float* __restrict__ fc_w,
                                                 const float* __restrict__ fc_b) {
    __shared__ float e_s[KCL * MID];
    const int b = blockIdx.x, j = threadIdx.x;
    for (int i = j; i < KCL * MID; i += 512) e_s[i] = g_emb0[b * (KCL * MID) + i];
    __syncthreads();
    float acc = 0.0f;
#pragma unroll 8
    for (int k = 0; k < KCL * MID; k++) acc += e_s[k] * fc_w[k * MID + j];
    g_h[b * MID + j] = acc + fc_b[j];
}

// ---------------- kernel 5: batchnorm (over batch) + relu -> embeddings ----------------
__global__ void __launch_bounds__(512) bn_kernel(const float* __restrict__ gamma,
                                                 const float* __restrict__ beta,
                                                 float* __restrict__ out) {
    const int j = threadIdx.x;
    float hv[BATCH];
    float s = 0.0f, s2 = 0.0f;
#pragma unroll
    for (int bb = 0; bb < BATCH; bb++) {
        float v = g_h[bb * MID + j];
        hv[bb] = v; s += v; s2 += v * v;
    }
    float mean = s * (1.0f / BATCH);
    float var  = s2 * (1.0f / BATCH) - mean * mean;
    float inv  = rsqrtf(var + 1e-5f);
    float ga = gamma[j], be = beta[j];
#pragma unroll
    for (int bb = 0; bb < BATCH; bb++) {
        float e = (hv[bb] - mean) * inv * ga + be;
        out[bb * MID + j] = fmaxf(e, 0.0f);
    }
}

// ---------------- kernel 6: vlad = embeddings @ logit_w ----------------
__global__ void __launch_bounds__(256) logit_kernel(const float* __restrict__ logit_w,
                                                    const float* __restrict__ emb,
                                                    float* __restrict__ out) {
    __shared__ __align__(16) float e_s[128][16];
    const int o  = blockIdx.x * 256 + threadIdx.x;
    const int b0 = blockIdx.y * 16;
    float acc[16];
#pragma unroll
    for (int i = 0; i < 16; i++) acc[i] = 0.0f;

    for (int c0 = 0; c0 < MID; c0 += 128) {
        __syncthreads();
        for (int i = threadIdx.x; i < 2048; i += 256) {
            int bi = i >> 7, cc = i & 127;
            e_s[cc][bi] = emb[(b0 + bi) * MID + c0 + cc];
        }
        __syncthreads();
        if (o < OUT_N) {
            for (int cc = 0; cc < 128; cc++) {
                float w = logit_w[(c0 + cc) * OUT_N + o];
                const float4 e0 = *(const float4*)&e_s[cc][0];
                const float4 e1 = *(const float4*)&e_s[cc][4];
                const float4 e2 = *(const float4*)&e_s[cc][8];
                const float4 e3 = *(const float4*)&e_s[cc][12];
                acc[0]  += e0.x * w; acc[1]  += e0.y * w; acc[2]  += e0.z * w; acc[3]  += e0.w * w;
                acc[4]  += e1.x * w; acc[5]  += e1.y * w; acc[6]  += e1.z * w; acc[7]  += e1.w * w;
                acc[8]  += e2.x * w; acc[9]  += e2.y * w; acc[10] += e2.z * w; acc[11] += e2.w * w;
                acc[12] += e3.x * w; acc[13] += e3.y * w; acc[14] += e3.z * w; acc[15] += e3.w * w;
            }
        }
    }
    if (o < OUT_N) {
#pragma unroll
        for (int bi = 0; bi < 16; bi++)
            out[(b0 + bi) * OUT_N + o] = acc[bi];
    }
}

// ---------------- launch ----------------
extern "C" void kernel_launch(void* const* d_in, const int* in_sizes, int n_in,
                              void* d_out, int out_size) {
    const float* features  = (const float*)d_in[0];
    const float* conv_w    = (const float*)d_in[1];
    const float* conv_b    = (const float*)d_in[2];
    const float* cc_w      = (const float*)d_in[3];
    const float* cc_b      = (const float*)d_in[4];
    const float* centroids = (const float*)d_in[5];
    const float* fc_w      = (const float*)d_in[6];
    const float* fc_b      = (const float*)d_in[7];
    const float* bn_gamma  = (const float*)d_in[8];
    const float* bn_beta   = (const float*)d_in[9];
    const float* logit_w   = (const float*)d_in[10];
    float* out = (float*)d_out;

    prep_weights<<<(KTOT * NPAD + 255) / 256, 256>>>(conv_w, cc_w);
    conv_gemm<<<dim3(NPAD / BN, 4, BATCH), 256>>>(features, conv_b, cc_b);
    agg_kernel<<<dim3(BATCH, 5), 512>>>();
    cluster_kernel<<<dim3(BATCH, KCL), 512>>>(centroids);
    fc_kernel<<<BATCH, 512>>>(fc_w, fc_b);
    bn_kernel<<<1, 512>>>(bn_gamma, bn_beta, out);
    logit_kernel<<<dim3(24, 2), 256>>>(logit_w, out, out + BATCH * MID);
}

// round 5
// speedup vs baseline: 1.3995x; 1.3995x over previous
#include <cuda_runtime.h>
#include <cstdint>

#define NCL 10
#define KCL 8
#define MID 512
#define OUT_N 5994
#define BATCH 32
#define WW 500
#define KTOT 3584
#define NPAD 576
#define MROWS 16000
#define KSLICE 8

// ---------------- scratch (__device__ globals; no allocations) ----------------
__device__ float g_Wt[KTOT * NPAD];            // 8.3 MB  pre-rounded tf32 weights, k-major
__device__ float g_feat[MROWS * MID];          // 32.8 MB relu(conv) output
__device__ float g_score[MROWS * NCL];         // 0.64 MB cc scores
__device__ float g_aggP[BATCH * 5 * NCL * MID];// partial aggregations (5 w-chunks)
__device__ float g_saP[BATCH * 5 * NCL];
__device__ float g_emb0[BATCH * KCL * MID];
__device__ float g_hP[KSLICE * BATCH * MID];   // fc split-K partials

__device__ __forceinline__ uint32_t f2tf32(float x) {
    uint32_t r;
    asm("cvt.rna.tf32.f32 %0, %1;" : "=r"(r) : "f"(x));
    return r;
}
__device__ __forceinline__ uint32_t smem_u32(const void* p) {
    return (uint32_t)__cvta_generic_to_shared(p);
}
__device__ __forceinline__ void cp16(uint32_t dst, const void* src, int srcsize) {
    asm volatile("cp.async.cg.shared.global [%0], [%1], 16, %2;"
                 :: "r"(dst), "l"(src), "r"(srcsize));
}

// ---------------- dummies: shift conv_gemm to global launch #5 for ncu -s 5 ----------------
__global__ void dummy_k() {}

// ---------------- kernel 0: tiled transpose + tf32-round weights (coalesced) ----------------
// reads W[n][k] (k contiguous), writes g_Wt[k][n] (n contiguous)
__global__ void __launch_bounds__(256) prep_weights(const float* __restrict__ conv_w,
                                                    const float* __restrict__ cc_w) {
    __shared__ float t_s[32][33];
    const int k0 = blockIdx.x * 32;
    const int n0 = blockIdx.y * 32;
    const int tx = threadIdx.x & 31;
    const int ty = threadIdx.x >> 5;   // 0..7
#pragma unroll
    for (int i = 0; i < 4; i++) {
        int n = n0 + ty + i * 8;
        int k = k0 + tx;
        float v = 0.0f;
        if (n < MID)            v = conv_w[n * KTOT + k];
        else if (n < MID + NCL) v = cc_w[(n - MID) * KTOT + k];
        t_s[tx][ty + i * 8] = v;       // t_s[k_local][n_local]
    }
    __syncthreads();
#pragma unroll
    for (int i = 0; i < 4; i++) {
        int k = k0 + ty + i * 8;
        g_Wt[k * NPAD + n0 + tx] = __uint_as_float(f2tf32(t_s[ty + i * 8][tx]));
    }
}

// ---------------- kernel 1: main GEMM (conv + cc fused), TF32 mma.sync ----------------
#define BM 128
#define BN 64
#define BK 16
#define NSTAGE 3
#define ASTR 136   // BM+8 : stride ≡ 8 (mod 32) -> conflict-free frag loads
#define BSTR 72    // BN+8
#define NSTEPS (KTOT / BK)   // 224

__global__ void __launch_bounds__(256) conv_gemm(const float* __restrict__ feats,
                                                 const float* __restrict__ conv_b,
                                                 const float* __restrict__ cc_b) {
    __shared__ __align__(16) float As[NSTAGE][BK][ASTR];
    __shared__ __align__(16) float Bs[NSTAGE][BK][BSTR];

    const int tid = threadIdx.x;
    const int b  = blockIdx.z;
    const int w0 = blockIdx.y * BM;
    const int n0 = blockIdx.x * BN;

    const float* Abase = feats + b * 1792000 + w0;   // b * 512*7*500

    // A loader: 2 passes of (8 k-rows x 32 float4)
    const int a_row  = tid >> 5;       // 0..7
    const int a_col4 = tid & 31;
    const int wlocal = a_col4 * 4;
    const int a_sz   = (w0 + wlocal + 3 < WW) ? 16 : 0;
    // B loader: 16 k-rows x 16 float4, one per thread
    const int b_row  = tid >> 4;
    const int b_col4 = tid & 15;

    auto load_stage = [&](int s, int step) {
        int k0 = step * BK;
#pragma unroll
        for (int p = 0; p < 2; p++) {
            int row = a_row + p * 8;
            int k = k0 + row;
            int c = k / 7;
            int h = k - c * 7;
            const float* src = a_sz ? (Abase + c * 3500 + h * 500 + wlocal) : Abase;
            cp16(smem_u32(&As[s][row][wlocal]), src, a_sz);
        }
        const float* bsrc = &g_Wt[(k0 + b_row) * NPAD + n0 + b_col4 * 4];
        cp16(smem_u32(&Bs[s][b_row][b_col4 * 4]), bsrc, 16);
        asm volatile("cp.async.commit_group;");
    };

    const int lane = tid & 31, warp = tid >> 5;
    const int g = lane >> 2, t = lane & 3;
    const int wm = (warp >> 1) * 32;   // 4 warps along M
    const int wn = (warp & 1) * 32;    // 2 warps along N

    float acc[2][4][4];
#pragma unroll
    for (int mi = 0; mi < 2; mi++)
#pragma unroll
        for (int ni = 0; ni < 4; ni++)
#pragma unroll
            for (int r = 0; r < 4; r++) acc[mi][ni][r] = 0.0f;

    load_stage(0, 0);
    load_stage(1, 1);

    for (int s = 0; s < NSTEPS; s++) {
        if (s < NSTEPS - 1) { asm volatile("cp.async.wait_group 1;"); }
        else                { asm volatile("cp.async.wait_group 0;"); }
        __syncthreads();
        const int sb = s % NSTAGE;
#pragma unroll
        for (int kk = 0; kk < BK; kk += 8) {
            uint32_t af[2][4], bf[4][2];
            // A fed as raw fp32 bits (HW tf32 truncation) — error budget verified
#pragma unroll
            for (int mi = 0; mi < 2; mi++) {
                af[mi][0] = __float_as_uint(As[sb][kk + t    ][wm + mi * 16 + g    ]);
                af[mi][1] = __float_as_uint(As[sb][kk + t    ][wm + mi * 16 + g + 8]);
                af[mi][2] = __float_as_uint(As[sb][kk + t + 4][wm + mi * 16 + g    ]);
                af[mi][3] = __float_as_uint(As[sb][kk + t + 4][wm + mi * 16 + g + 8]);
            }
#pragma unroll
            for (int ni = 0; ni < 4; ni++) {
                bf[ni][0] = __float_as_uint(Bs[sb][kk + t    ][wn + ni * 8 + g]);
                bf[ni][1] = __float_as_uint(Bs[sb][kk + t + 4][wn + ni * 8 + g]);
            }
#pragma unroll
            for (int mi = 0; mi < 2; mi++)
#pragma unroll
                for (int ni = 0; ni < 4; ni++) {
                    asm volatile(
                        "mma.sync.aligned.m16n8k8.row.col.f32.tf32.tf32.f32 "
                        "{%0,%1,%2,%3}, {%4,%5,%6,%7}, {%8,%9}, {%0,%1,%2,%3};"
                        : "+f"(acc[mi][ni][0]), "+f"(acc[mi][ni][1]),
                          "+f"(acc[mi][ni][2]), "+f"(acc[mi][ni][3])
                        : "r"(af[mi][0]), "r"(af[mi][1]), "r"(af[mi][2]), "r"(af[mi][3]),
                          "r"(bf[ni][0]), "r"(bf[ni][1]));
                }
        }
        if (s + 2 < NSTEPS) load_stage((s + 2) % NSTAGE, s + 2);
    }

    // epilogue: bias + relu -> g_feat, bias -> g_score
#pragma unroll
    for (int mi = 0; mi < 2; mi++) {
        int m0 = wm + mi * 16 + g;
#pragma unroll
        for (int ni = 0; ni < 4; ni++) {
            int n = n0 + wn + ni * 8 + 2 * t;
#pragma unroll
            for (int r = 0; r < 4; r++) {
                int mm = m0 + ((r >= 2) ? 8 : 0);
                int nn = n + (r & 1);
                int wg = w0 + mm;
                if (wg < WW) {
                    float v = acc[mi][ni][r];
                    if (nn < MID) {
                        v += conv_b[nn];
                        g_feat[(b * WW + wg) * MID + nn] = fmaxf(v, 0.0f);
                    } else if (nn < MID + NCL) {
                        v += cc_b[nn - MID];
                        g_score[(b * WW + wg) * NCL + (nn - MID)] = v;
                    }
                }
            }
        }
    }
}

// ---------------- kernel 2: softmax + weighted aggregation (partial over w-chunks) ----------------
__global__ void __launch_bounds__(512) agg_kernel() {
    __shared__ float p_s[100][NCL];
    const int b = blockIdx.x, chunk = blockIdx.y;
    const int w_base = chunk * 100;
    const int tid = threadIdx.x;

    if (tid < 100) {
        const float* sc = &g_score[(b * WW + w_base + tid) * NCL];
        float v[NCL];
        float mx = -1e30f;
#pragma unroll
        for (int k = 0; k < NCL; k++) { v[k] = sc[k]; mx = fmaxf(mx, v[k]); }
        float s = 0.0f;
#pragma unroll
        for (int k = 0; k < NCL; k++) { v[k] = __expf(v[k] - mx); s += v[k]; }
        float inv = 1.0f / s;
#pragma unroll
        for (int k = 0; k < NCL; k++) p_s[tid][k] = v[k] * inv;
    }
    __syncthreads();

    if (tid < NCL) {
        float ss = 0.0f;
        for (int w = 0; w < 100; w++) ss += p_s[w][tid];
        g_saP[(b * 5 + chunk) * NCL + tid] = ss;
    }

    const int c = tid;   // 512 threads = MID channels
    float acc[NCL];
#pragma unroll
    for (int k = 0; k < NCL; k++) acc[k] = 0.0f;
#pragma unroll 4
    for (int w = 0; w < 100; w++) {
        float f = g_feat[(b * WW + w_base + w) * MID + c];
#pragma unroll
        for (int k = 0; k < NCL; k++) acc[k] += p_s[w][k] * f;
    }
#pragma unroll
    for (int k = 0; k < NCL; k++)
        g_aggP[((b * 5 + chunk) * NCL + k) * MID + c] = acc[k];
}

// ---------------- kernel 3: residual + L2 normalize -> emb0 ----------------
__global__ void __launch_bounds__(512) cluster_kernel(const float* __restrict__ centroids) {
    const int b = blockIdx.x, k = blockIdx.y;   // k < 8
    const int c = threadIdx.x;
    float a = 0.0f;
#pragma unroll
    for (int ch = 0; ch < 5; ch++) a += g_aggP[((b * 5 + ch) * NCL + k) * MID + c];

    __shared__ float s_sa;
    __shared__ float s_red[16];
    if (c == 0) {
        float s = 0.0f;
#pragma unroll
        for (int ch = 0; ch < 5; ch++) s += g_saP[(b * 5 + ch) * NCL + k];
        s_sa = s;
    }
    __syncthreads();

    float r = a - s_sa * centroids[k * MID + c];
    float x = r * r;
#pragma unroll
    for (int off = 16; off > 0; off >>= 1) x += __shfl_xor_sync(0xffffffffu, x, off);
    int lane = c & 31, wid = c >> 5;
    if (lane == 0) s_red[wid] = x;
    __syncthreads();
    if (wid == 0) {
        float y = (lane < 16) ? s_red[lane] : 0.0f;
#pragma unroll
        for (int off = 8; off > 0; off >>= 1) y += __shfl_xor_sync(0xffffffffu, y, off);
        if (lane == 0) s_red[0] = y;
    }
    __syncthreads();
    float inv = 1.0f / fmaxf(sqrtf(s_red[0]), 1e-12f);
    g_emb0[b * (KCL * MID) + k * MID + c] = r * inv;
}

// ---------------- kernel 4: h partials = emb0 @ fc_w (split-K over 8 slices) ----------------
__global__ void __launch_bounds__(512) fc_kernel(const float* __restrict__ fc_w) {
    __shared__ float e_s[512];
    const int ks = blockIdx.x;     // 0..7 k-slice
    const int b  = blockIdx.y;
    const int j  = threadIdx.x;
    const int kbase = ks * 512;
    e_s[j] = g_emb0[b * (KCL * MID) + kbase + j];
    __syncthreads();
    float acc = 0.0f;
#pragma unroll 8
    for (int k = 0; k < 512; k++) acc += e_s[k] * fc_w[(kbase + k) * MID + j];
    g_hP[(ks * BATCH + b) * MID + j] = acc;
}

// ---------------- kernel 5: sum partials + bias + batchnorm + relu -> embeddings ----------------
__global__ void __launch_bounds__(512) bn_kernel(const float* __restrict__ fc_b,
                                                 const float* __restrict__ gamma,
                                                 const float* __restrict__ beta,
                                                 float* __restrict__ out) {
    const int j = threadIdx.x;
    float hv[BATCH];
    float s = 0.0f, s2 = 0.0f;
    const float bias = fc_b[j];
#pragma unroll
    for (int bb = 0; bb < BATCH; bb++) {
        float v = bias;
#pragma unroll
        for (int ks = 0; ks < KSLICE; ks++) v += g_hP[(ks * BATCH + bb) * MID + j];
        hv[bb] = v; s += v; s2 += v * v;
    }
    float mean = s * (1.0f / BATCH);
    float var  = s2 * (1.0f / BATCH) - mean * mean;
    float inv  = rsqrtf(var + 1e-5f);
    float ga = gamma[j], be = beta[j];
#pragma unroll
    for (int bb = 0; bb < BATCH; bb++) {
        float e = (hv[bb] - mean) * inv * ga + be;
        out[bb * MID + j] = fmaxf(e, 0.0f);
    }
}

// ---------------- kernel 6: vlad = embeddings @ logit_w ----------------
__global__ void __launch_bounds__(256) logit_kernel(const float* __restrict__ logit_w,
                                                    const float* __restrict__ emb,
                                                    float* __restrict__ out) {
    __shared__ __align__(16) float e_s[128][16];
    const int o  = blockIdx.x * 256 + threadIdx.x;
    const int b0 = blockIdx.y * 16;
    float acc[16];
#pragma unroll
    for (int i = 0; i < 16; i++) acc[i] = 0.0f;

    for (int c0 = 0; c0 < MID; c0 += 128) {
        __syncthreads();
        for (int i = threadIdx.x; i < 2048; i += 256) {
            int bi = i >> 7, cc = i & 127;
            e_s[cc][bi] = emb[(b0 + bi) * MID + c0 + cc];
        }
        __syncthreads();
        if (o < OUT_N) {
#pragma unroll 4
            for (int cc = 0; cc < 128; cc++) {
                float w = logit_w[(c0 + cc) * OUT_N + o];
                const float4 e0 = *(const float4*)&e_s[cc][0];
                const float4 e1 = *(const float4*)&e_s[cc][4];
                const float4 e2 = *(const float4*)&e_s[cc][8];
                const float4 e3 = *(const float4*)&e_s[cc][12];
                acc[0]  += e0.x * w; acc[1]  += e0.y * w; acc[2]  += e0.z * w; acc[3]  += e0.w * w;
                acc[4]  += e1.x * w; acc[5]  += e1.y * w; acc[6]  += e1.z * w; acc[7]  += e1.w * w;
                acc[8]  += e2.x * w; acc[9]  += e2.y * w; acc[10] += e2.z * w; acc[11] += e2.w * w;
                acc[12] += e3.x * w; acc[13] += e3.y * w; acc[14] += e3.z * w; acc[15] += e3.w * w;
            }
        }
    }
    if (o < OUT_N) {
#pragma unroll
        for (int bi = 0; bi < 16; bi++)
            out[(b0 + bi) * OUT_N + o] = acc[bi];
    }
}

// ---------------- launch ----------------
extern "C" void kernel_launch(void* const* d_in, const int* in_sizes, int n_in,
                              void* d_out, int out_size) {
    const float* features  = (const float*)d_in[0];
    const float* conv_w    = (const float*)d_in[1];
    const float* conv_b    = (const float*)d_in[2];
    const float* cc_w      = (const float*)d_in[3];
    const float* cc_b      = (const float*)d_in[4];
    const float* centroids = (const float*)d_in[5];
    const float* fc_w      = (const float*)d_in[6];
    const float* fc_b      = (const float*)d_in[7];
    const float* bn_gamma  = (const float*)d_in[8];
    const float* bn_beta   = (const float*)d_in[9];
    const float* logit_w   = (const float*)d_in[10];
    float* out = (float*)d_out;

    prep_weights<<<dim3(KTOT / 32, NPAD / 32), 256>>>(conv_w, cc_w);
    dummy_k<<<1, 32>>>();
    dummy_k<<<1, 32>>>();   // pads conv_gemm to global launch #5 for ncu -s 5 -c 1
    conv_gemm<<<dim3(NPAD / BN, 4, BATCH), 256>>>(features, conv_b, cc_b);
    agg_kernel<<<dim3(BATCH, 5), 512>>>();
    cluster_kernel<<<dim3(BATCH, KCL), 512>>>(centroids);
    fc_kernel<<<dim3(KSLICE, BATCH), 512>>>(fc_w);
    bn_kernel<<<1, 512>>>(fc_b, bn_gamma, bn_beta, out);
    logit_kernel<<<dim3(24, 2), 256>>>(logit_w, out, out + BATCH * MID);
}